// round 17
// baseline (speedup 1.0000x reference)
#include <cuda_runtime.h>
#include <cuda_fp16.h>
#include <cstdint>

// ---------------------------------------------------------------------------
// CliffordEPModel collapsed:
//   pred[b,o] = sum_{ma} x[b,ma] * A[ma,o]                           (main MMA)
//   A[ma,o]   = c * sum_{hk} coef(a,k) * Win[h, m*8+(a^k)] * Wout[o, hk]
//   c = 1 - 0.9^20 ;  coef(a,k) = sgn(k,k)*sgn(a,a^k)  (Cl(3,0) Cayley)
// SINGLE fused launch: CTA roles (prep GEMM -> reduce/pack -> main GEMM)
// chained with release/acquire counters. Saves 2 kernel-launch overheads.
// Prep A-staging now XOR-swizzled (kills 8-way STS bank conflicts).
// ---------------------------------------------------------------------------

#define NSLICE  16                      // split-K for prep (hk slices of 256)
#define C_RELAX 0.8784233454094307f     // 1 - 0.9^20

#define PREP_CTAS 256
#define RED_CTAS  64
#define MAIN_CTAS 64
#define TOTAL_CTAS (PREP_CTAS + RED_CTAS + MAIN_CTAS)

// scratch
__device__ __align__(16) float g_P[NSLICE][512 * 64];   // prep partials [ma][o], 2 MB
__device__ __align__(16) uint4 g_Bpk[4096];             // packed fp16 B-frags, 64 KB
__device__ int g_prep_done, g_red_done, g_main_started, g_main_done;

__device__ __forceinline__ float blade_sign(int a, int b) {
    int e = (b & 1) * (((a >> 1) & 1) + ((a >> 2) & 1)) + ((b >> 1) & 1) * ((a >> 2) & 1);
    return (e & 1) ? -1.0f : 1.0f;
}

__device__ __forceinline__ uint32_t smem_u32(const void* p) {
    uint32_t a;
    asm("{ .reg .u64 t; cvta.to.shared.u64 t, %1; cvt.u32.u64 %0, t; }" : "=r"(a) : "l"(p));
    return a;
}

__device__ __forceinline__ void ldsm_x4(uint32_t* r, uint32_t addr) {
    asm volatile("ldmatrix.sync.aligned.m8n8.x4.shared.b16 {%0,%1,%2,%3}, [%4];"
                 : "=r"(r[0]), "=r"(r[1]), "=r"(r[2]), "=r"(r[3]) : "r"(addr));
}

__device__ __forceinline__ void mma_fp16(float* c, const uint32_t* a, uint32_t b0, uint32_t b1) {
    asm volatile(
        "mma.sync.aligned.m16n8k16.row.col.f32.f16.f16.f32 "
        "{%0,%1,%2,%3}, {%4,%5,%6,%7}, {%8,%9}, {%0,%1,%2,%3};"
        : "+f"(c[0]), "+f"(c[1]), "+f"(c[2]), "+f"(c[3])
        : "r"(a[0]), "r"(a[1]), "r"(a[2]), "r"(a[3]), "r"(b0), "r"(b1));
}

__device__ __forceinline__ uint32_t h2pack(float lo, float hi) {
    __half2 h = __floats2half2_rn(lo, hi);
    return *reinterpret_cast<uint32_t*>(&h);
}

__device__ __forceinline__ int ld_acq(const int* p) {
    int v;
    asm volatile("ld.acquire.gpu.b32 %0, [%1];" : "=r"(v) : "l"(p) : "memory");
    return v;
}

#define P_ROW    528
#define P_AS     0
#define P_BS     (64 * P_ROW)
#define PREP_SMEM (96 * P_ROW)          // 50688

__global__ __launch_bounds__(256, 2) void fused_kernel(
        const float* __restrict__ Win, const float* __restrict__ Wout,
        const float* __restrict__ X, float* __restrict__ out) {
    extern __shared__ char sm[];
    int bid = blockIdx.x;
    int tid = threadIdx.x;

    if (bid < PREP_CTAS) {
        // ================= PREP role: split-K GEMM tile =================
        // grid decomp: x = bid&7 (ma-tile), y = (bid>>3)&1 (o-tile), z = bid>>4
        int bx = bid & 7, by = (bid >> 3) & 1, s = bid >> 4;
        int w = tid >> 5, l = tid & 31;
        int ma0 = bx * 64;
        int ob0 = by * 32;

        // ---- issue ALL global loads first (MLP) ----
        float4 bv[8];
#pragma unroll
        for (int it = 0; it < 8; it++) {
            int idx = it * 256 + tid;   // float4 units
            int row = idx >> 6;         // o-local 0..31
            int c4  = idx & 63;
            bv[it] = *(const float4*)&Wout[(ob0 + row) * 4096 + s * 256 + c4 * 4];
        }
        int m_local = tid & 7;
        int h_local = tid >> 3;         // 0..31
        int h  = s * 32 + h_local;
        int mg = bx * 8 + m_local;
        float4 w0 = *(const float4*)&Win[h * 512 + mg * 8];
        float4 w1 = *(const float4*)&Win[h * 512 + mg * 8 + 4];

        // ---- convert + store B tile (coalesced, conflict-free) ----
#pragma unroll
        for (int it = 0; it < 8; it++) {
            int idx = it * 256 + tid;
            int row = idx >> 6;
            int c4  = idx & 63;
            uint2 pk = make_uint2(h2pack(bv[it].x, bv[it].y), h2pack(bv[it].z, bv[it].w));
            *(uint2*)(sm + P_BS + row * P_ROW + c4 * 8) = pk;
        }
        // ---- convert + store A tile (Cayley gather, XOR-swizzled cols) ----
        {
            float w8[8] = {w0.x, w0.y, w0.z, w0.w, w1.x, w1.y, w1.z, w1.w};
#pragma unroll
            for (int a = 0; a < 8; a++) {
                __half hv[8];
#pragma unroll
                for (int k = 0; k < 8; k++) {
                    float coef = blade_sign(k, k) * blade_sign(a, a ^ k);
                    hv[k] = __float2half_rn(coef * w8[a ^ k]);
                }
                // swizzle: col16' = h_local ^ m_local (row>>3 == m_local)
                *(uint4*)(sm + P_AS + (m_local * 8 + a) * P_ROW + (h_local ^ m_local) * 16) =
                    *reinterpret_cast<uint4*>(hv);
            }
        }
        __syncthreads();

        // ---- compute: 8 warps = 4 m-groups x 2 n-groups; K=256, 4 chunks ----
        int mg2 = w & 3, ng = w >> 2;
        int grp = l >> 3, rin = l & 7;
        uint32_t smb = smem_u32(sm);
        int arow = mg2 * 16 + rin + (grp & 1) * 8;
        int rowm = (arow >> 3) & 7;
        uint32_t aRow = smb + P_AS + (uint32_t)(arow * P_ROW);
        uint32_t swk[4];
#pragma unroll
        for (int ks = 0; ks < 4; ks++)
            swk[ks] = (uint32_t)((((grp >> 1) + ks * 2) ^ rowm) * 16);
        uint32_t bB0 = smb + P_BS + (uint32_t)((ng * 16 + rin) * P_ROW + grp * 16);

        float acc[2][4];
#pragma unroll
        for (int t = 0; t < 2; t++)
#pragma unroll
            for (int q = 0; q < 4; q++) acc[t][q] = 0.f;

#pragma unroll
        for (int cc = 0; cc < 4; cc++) {
            uint32_t Af[4][4];
#pragma unroll
            for (int ks = 0; ks < 4; ks++) ldsm_x4(Af[ks], aRow + cc * 128 + swk[ks]);
#pragma unroll
            for (int t = 0; t < 2; t++) {
                uint32_t bf[8];
                uint32_t bB = bB0 + (uint32_t)(t * 8 * P_ROW + cc * 128);
#pragma unroll
                for (int kp = 0; kp < 2; kp++) ldsm_x4(&bf[kp * 4], bB + kp * 64);
#pragma unroll
                for (int ks = 0; ks < 4; ks++)
                    mma_fp16(acc[t], Af[ks], bf[ks * 2], bf[ks * 2 + 1]);
            }
        }

        // ---- epilogue + publish ----
        float* dst = g_P[s];
        int ma_r = ma0 + mg2 * 16 + (l >> 2);
        int o_c  = ob0 + ng * 16 + (l & 3) * 2;
#pragma unroll
        for (int t = 0; t < 2; t++) {
            *(float2*)&dst[ma_r * 64 + o_c + t * 8]       = make_float2(acc[t][0], acc[t][1]);
            *(float2*)&dst[(ma_r + 8) * 64 + o_c + t * 8] = make_float2(acc[t][2], acc[t][3]);
        }
        __threadfence();
        __syncthreads();
        if (tid == 0) atomicAdd(&g_prep_done, 1);

    } else if (bid < PREP_CTAS + RED_CTAS) {
        // ================= REDUCE role =================
        if (tid == 0) {
            while (ld_acq(&g_prep_done) < PREP_CTAS) __nanosleep(64);
        }
        __syncthreads();

        int e = (bid - PREP_CTAS) * 256 + tid;    // 0..16383
        int o = e & 63;
        int j = e >> 6;                            // k-pair (k = 2j over ma)
        float s0 = 0.f, s1 = 0.f;
#pragma unroll
        for (int s = 0; s < NSLICE; s++) {
            s0 += g_P[s][(2 * j) * 64 + o];
            s1 += g_P[s][(2 * j + 1) * 64 + o];
        }
        uint32_t hv = h2pack(s0 * C_RELAX, s1 * C_RELAX);

        int k   = 2 * j;
        int i   = k >> 6;
        int r   = k & 63;
        int ks  = r >> 4;
        int rem = r & 15;
        int cc  = rem >> 2;
        int comp = (ks & 1) * 2 + ((rem & 2) >> 1);
        int kp  = ks >> 1;
        int nt  = o >> 3;
        int lI  = ((o & 7) << 2) | cc;
        ((uint32_t*)g_Bpk)[((((i * 8 + nt) * 2 + kp) * 32) + lI) * 4 + comp] = hv;

        __threadfence();
        __syncthreads();
        if (tid == 0) atomicAdd(&g_red_done, 1);

    } else {
        // ================= MAIN role =================
        if (tid == 0) {
            while (ld_acq(&g_red_done) < RED_CTAS) __nanosleep(64);
            atomicAdd(&g_main_started, 1);
        }
        __syncthreads();

        int w = tid >> 5, l = tid & 31;
        int W = (bid - PREP_CTAS - RED_CTAS) * 8 + w;   // 0..511
        int c = l & 3, rY = l >> 2;
        int r0 = W * 16;

        float acc[8][4];
#pragma unroll
        for (int nt = 0; nt < 8; nt++)
#pragma unroll
            for (int q = 0; q < 4; q++) acc[nt][q] = 0.f;

        const float* x0 = X + (r0 + rY) * 512 + 4 * c;
        const float* x1 = x0 + 8 * 512;

        float4 lo[4], hi[4];
#pragma unroll
        for (int ks = 0; ks < 4; ks++) {
            lo[ks] = *(const float4*)(x0 + ks * 16);
            hi[ks] = *(const float4*)(x1 + ks * 16);
        }

#pragma unroll
        for (int i = 0; i < 8; i++) {
            uint32_t A[4][4];
#pragma unroll
            for (int ks = 0; ks < 4; ks++) {
                A[ks][0] = h2pack(lo[ks].x, lo[ks].y);
                A[ks][1] = h2pack(hi[ks].x, hi[ks].y);
                A[ks][2] = h2pack(lo[ks].z, lo[ks].w);
                A[ks][3] = h2pack(hi[ks].z, hi[ks].w);
            }
            if (i < 7) {
                int k0 = (i + 1) * 64;
#pragma unroll
                for (int ks = 0; ks < 4; ks++) {
                    lo[ks] = *(const float4*)(x0 + k0 + ks * 16);
                    hi[ks] = *(const float4*)(x1 + k0 + ks * 16);
                }
            }
#pragma unroll
            for (int nt = 0; nt < 8; nt++) {
#pragma unroll
                for (int kp = 0; kp < 2; kp++) {
                    uint4 b = g_Bpk[((i * 8 + nt) * 2 + kp) * 32 + l];
                    mma_fp16(acc[nt], A[2 * kp],     b.x, b.y);
                    mma_fp16(acc[nt], A[2 * kp + 1], b.z, b.w);
                }
            }
        }

        int rr = r0 + rY;
        int cb = 2 * c;
#pragma unroll
        for (int nt = 0; nt < 8; nt++) {
            *(float2*)&out[rr * 64 + nt * 8 + cb]       = make_float2(acc[nt][0], acc[nt][1]);
            *(float2*)&out[(rr + 8) * 64 + nt * 8 + cb] = make_float2(acc[nt][2], acc[nt][3]);
        }

        // ---- reset counters for next (graph-replayed) run ----
        __syncthreads();
        if (tid == 0) {
            int r = atomicAdd(&g_main_done, 1);
            if (r == MAIN_CTAS - 1) {
                while (ld_acq(&g_main_started) < MAIN_CTAS) __nanosleep(32);
                g_prep_done = 0;
                g_red_done = 0;
                g_main_started = 0;
                g_main_done = 0;
                __threadfence();
            }
        }
    }
}

// ---------------------------------------------------------------------------
extern "C" void kernel_launch(void* const* d_in, const int* in_sizes, int n_in,
                              void* d_out, int out_size) {
    const float* x    = (const float*)d_in[0];   // (8192, 512)
    const float* Win  = (const float*)d_in[1];   // (512h, 512mb)
    const float* Wout = (const float*)d_in[2];   // (64, 4096)
    float* out        = (float*)d_out;           // (8192, 64)

    cudaFuncSetAttribute(fused_kernel,
                         cudaFuncAttributeMaxDynamicSharedMemorySize, PREP_SMEM);

    fused_kernel<<<TOTAL_CTAS, 256, PREP_SMEM>>>(Win, Wout, x, out);
}